// round 4
// baseline (speedup 1.0000x reference)
#include <cuda_runtime.h>
#include <cuda_bf16.h>
#include <cstdint>
#include <cstddef>

// Problem shape
#define BB   8
#define T1C  2048
#define T2C  2048
#define DD   256

// Tiling
#define TILE_M 128
#define TILE_N 128
#define N_JT   (T2C / TILE_N)     // 16
#define CAP    24                 // candidates per row
#define MARGIN 4.5f               // > 2 * bf16 score-error bound

// smem layout (bytes); A tile 64KB, B double buffer 2x64KB
#define SM_A    0
#define SM_B    65536
#define SM_CJ   196608
#define SM_CV   (SM_CJ + TILE_M * CAP * 4)   // 208896
#define SM_CNT  (SM_CV + TILE_M * CAP * 4)   // 221184
#define SM_RMX  (SM_CNT + 512)               // 221696
#define SMEM_TOTAL (SM_RMX + 512)            // 222208

__device__ __align__(1024) __nv_bfloat16 g_s1b[BB * T1C * DD];
__device__ __align__(1024) __nv_bfloat16 g_s2b[BB * T2C * DD];
__device__ int g_argmax[BB * T1C];

// ---------------------------------------------------------------------------
// PTX helpers (all compute_103-safe: sm_80-era instructions only)
// ---------------------------------------------------------------------------
static __device__ __forceinline__ uint32_t smem_to_u32(const void* p) {
    uint32_t a;
    asm("{ .reg .u64 t; cvta.to.shared.u64 t, %1; cvt.u32.u64 %0, t; }"
        : "=r"(a) : "l"(p));
    return a;
}
static __device__ __forceinline__ void cp16(uint32_t dst, const void* src) {
    asm volatile("cp.async.cg.shared.global [%0], [%1], 16;"
                 :: "r"(dst), "l"(src));
}
#define CP_COMMIT() asm volatile("cp.async.commit_group;" ::: "memory")
#define CP_WAIT0()  asm volatile("cp.async.wait_group 0;" ::: "memory")

#define LDSM_X4(r0, r1, r2, r3, addr) \
    asm volatile("ldmatrix.sync.aligned.m8n8.x4.shared.b16 {%0,%1,%2,%3}, [%4];" \
        : "=r"(r0), "=r"(r1), "=r"(r2), "=r"(r3) : "r"(addr))

#define MMA16816(d, a, b) \
    asm volatile("mma.sync.aligned.m16n8k16.row.col.f32.bf16.bf16.f32 " \
        "{%0,%1,%2,%3}, {%4,%5,%6,%7}, {%8,%9}, {%0,%1,%2,%3};" \
        : "+f"((d)[0]), "+f"((d)[1]), "+f"((d)[2]), "+f"((d)[3]) \
        : "r"((a)[0]), "r"((a)[1]), "r"((a)[2]), "r"((a)[3]), \
          "r"((b)[0]), "r"((b)[1]))

// order-preserving float<->uint encoding for atomicMax
static __device__ __forceinline__ unsigned enc(float x) {
    unsigned u = __float_as_uint(x);
    return (u & 0x80000000u) ? ~u : (u | 0x80000000u);
}
static __device__ __forceinline__ float dec(unsigned u) {
    return __uint_as_float((u & 0x80000000u) ? (u & 0x7FFFFFFFu) : ~u);
}

// ---------------------------------------------------------------------------
// fp32 -> bf16 conversion of both inputs
// ---------------------------------------------------------------------------
static __device__ __forceinline__ uint32_t f2bf2(float x, float y) {
    __nv_bfloat162 h = __float22bfloat162_rn(make_float2(x, y));
    return *reinterpret_cast<uint32_t*>(&h);
}

__global__ void __launch_bounds__(256)
convert_kernel(const float4* __restrict__ s1, const float4* __restrict__ s2)
{
    size_t t = (size_t)blockIdx.x * 256 + threadIdx.x;   // 0 .. 524287
    float4 a0 = s1[2 * t], a1 = s1[2 * t + 1];
    float4 b0 = s2[2 * t], b1 = s2[2 * t + 1];
    uint4 oa, ob;
    oa.x = f2bf2(a0.x, a0.y); oa.y = f2bf2(a0.z, a0.w);
    oa.z = f2bf2(a1.x, a1.y); oa.w = f2bf2(a1.z, a1.w);
    ob.x = f2bf2(b0.x, b0.y); ob.y = f2bf2(b0.z, b0.w);
    ob.z = f2bf2(b1.x, b1.y); ob.w = f2bf2(b1.z, b1.w);
    ((uint4*)g_s1b)[t] = oa;
    ((uint4*)g_s2b)[t] = ob;
}

// ---------------------------------------------------------------------------
// exact fp32 dot of two 256-float rows
// ---------------------------------------------------------------------------
static __device__ float dot256(const float4* __restrict__ a,
                               const float4* __restrict__ b)
{
    float a0 = 0.f, a1 = 0.f, a2 = 0.f, a3 = 0.f;
    #pragma unroll 8
    for (int k = 0; k < DD / 4; k++) {
        float4 x = __ldg(a + k);
        float4 y = __ldg(b + k);
        a0 = fmaf(x.x, y.x, a0);
        a1 = fmaf(x.y, y.y, a1);
        a2 = fmaf(x.z, y.z, a2);
        a3 = fmaf(x.w, y.w, a3);
    }
    return (a0 + a1) + (a2 + a3);
}

// ---------------------------------------------------------------------------
// bf16 HMMA GEMM (mma.sync) with argmax-candidate epilogue + fp32 refine.
// Grid (16, 8): blockIdx.x = 128-row i-tile, blockIdx.y = batch.
// 8 warps, each computing a 64x32 sub-tile (2x4 warp grid over 128x128).
// ---------------------------------------------------------------------------
__global__ void __launch_bounds__(256, 1)
mma_argmax_kernel(const float* __restrict__ s1, const float* __restrict__ s2)
{
    extern __shared__ __align__(1024) char smem[];
    const uint32_t sb = smem_to_u32(smem);
    int*      cj  = (int*)(smem + SM_CJ);
    float*    cv  = (float*)(smem + SM_CV);
    unsigned* cnt = (unsigned*)(smem + SM_CNT);
    unsigned* rmx = (unsigned*)(smem + SM_RMX);

    const int tid  = threadIdx.x;
    const int wid  = tid >> 5, lane = tid & 31;
    const int wm   = wid >> 2, wn = wid & 3;       // warp grid 2(m) x 4(n)
    const int q    = lane >> 3, rr = lane & 7;     // ldmatrix quad / row
    const int gID  = lane >> 2, t4 = lane & 3;     // mma fragment coords
    const int b    = blockIdx.y;
    const int i0   = blockIdx.x * TILE_M;

    if (tid < TILE_M) { cnt[tid] = 0u; rmx[tid] = 0x007FFFFFu; }  // enc(-inf)

    const char* gA = (const char*)(g_s1b + ((size_t)b * T1C + i0) * DD);
    const char* gB = (const char*)(g_s2b + (size_t)b * T2C * DD);

    // Stage full A tile (128 x 256 bf16, 512B rows) with 16B-chunk XOR swizzle
    #pragma unroll
    for (int it = 0; it < 16; it++) {
        int f = it * 256 + tid, row = f >> 5, c = f & 31;
        cp16(sb + SM_A + row * 512 + ((c ^ (row & 7)) << 4),
             gA + (size_t)row * 512 + (size_t)c * 16);
    }
    CP_COMMIT();
    // Stage B tile 0
    #pragma unroll
    for (int it = 0; it < 16; it++) {
        int f = it * 256 + tid, row = f >> 5, c = f & 31;
        cp16(sb + SM_B + row * 512 + ((c ^ (row & 7)) << 4),
             gB + (size_t)row * 512 + (size_t)c * 16);
    }
    CP_COMMIT();
    CP_WAIT0();
    __syncthreads();

    // ldmatrix base addresses.
    // A m16k16 frag: matrix q -> row += (q&1)*8, kchunk += (q>>1)
    uint32_t aBase[4]; int aSw[4];
    #pragma unroll
    for (int mf = 0; mf < 4; mf++) {
        int arow = wm * 64 + mf * 16 + (q & 1) * 8 + rr;
        aBase[mf] = sb + SM_A + arow * 512;
        aSw[mf]   = arow & 7;
    }
    // B n16k16 frag: matrix q -> row += (q>>1)*8, kchunk += (q&1)
    uint32_t bRow[2]; int bSw[2];
    #pragma unroll
    for (int bf = 0; bf < 2; bf++) {
        int brow = wn * 32 + bf * 16 + (q >> 1) * 8 + rr;
        bRow[bf] = brow * 512;
        bSw[bf]  = brow & 7;
    }
    const int qh = q >> 1, ql = q & 1;

    #pragma unroll 1
    for (int jc = 0; jc < N_JT; jc++) {
        const int buf = jc & 1;
        const int j0  = jc * TILE_N;

        // prefetch next B tile into the other buffer
        if (jc + 1 < N_JT) {
            const char* gBt = gB + (size_t)(j0 + TILE_N) * 512;
            #pragma unroll
            for (int it = 0; it < 16; it++) {
                int f = it * 256 + tid, row = f >> 5, c = f & 31;
                cp16(sb + SM_B + (buf ^ 1) * 65536 + row * 512 +
                         ((c ^ (row & 7)) << 4),
                     gBt + (size_t)row * 512 + (size_t)c * 16);
            }
            CP_COMMIT();
        }

        float acc[4][4][4];
        #pragma unroll
        for (int mf = 0; mf < 4; mf++)
            #pragma unroll
            for (int nf = 0; nf < 4; nf++)
                #pragma unroll
                for (int e = 0; e < 4; e++) acc[mf][nf][e] = 0.f;

        const uint32_t bBase = sb + SM_B + buf * 65536;
        #pragma unroll
        for (int ks = 0; ks < 16; ks++) {
            uint32_t a[4][4];
            #pragma unroll
            for (int mf = 0; mf < 4; mf++) {
                uint32_t ad = aBase[mf] +
                    (uint32_t)((((2 * ks + qh) ^ aSw[mf])) << 4);
                LDSM_X4(a[mf][0], a[mf][1], a[mf][2], a[mf][3], ad);
            }
            uint32_t bb[4][2];
            #pragma unroll
            for (int bf = 0; bf < 2; bf++) {
                uint32_t bd = bBase + bRow[bf] +
                    (uint32_t)((((2 * ks + ql) ^ bSw[bf])) << 4);
                LDSM_X4(bb[2 * bf][0], bb[2 * bf][1],
                        bb[2 * bf + 1][0], bb[2 * bf + 1][1], bd);
            }
            #pragma unroll
            for (int mf = 0; mf < 4; mf++)
                #pragma unroll
                for (int nf = 0; nf < 4; nf++)
                    MMA16816(acc[mf][nf], a[mf], bb[nf]);
        }

        // ---- fold phase A: per-row running max (order-preserving atomicMax)
        #pragma unroll
        for (int mf = 0; mf < 4; mf++)
            #pragma unroll
            for (int h = 0; h < 2; h++) {
                float m = acc[mf][0][2 * h];
                #pragma unroll
                for (int nf = 0; nf < 4; nf++) {
                    m = fmaxf(m, acc[mf][nf][2 * h]);
                    m = fmaxf(m, acc[mf][nf][2 * h + 1]);
                }
                int row = wm * 64 + mf * 16 + h * 8 + gID;
                atomicMax(&rmx[row], enc(m));
            }
        __syncthreads();

        // ---- fold phase B: collect candidates within margin of running max
        #pragma unroll
        for (int mf = 0; mf < 4; mf++)
            #pragma unroll
            for (int h = 0; h < 2; h++) {
                int row = wm * 64 + mf * 16 + h * 8 + gID;
                float thr = dec(rmx[row]) - MARGIN;
                #pragma unroll
                for (int nf = 0; nf < 4; nf++)
                    #pragma unroll
                    for (int cp = 0; cp < 2; cp++) {
                        float v = acc[mf][nf][2 * h + cp];
                        if (v >= thr) {
                            unsigned slot = atomicAdd(&cnt[row], 1u);
                            if (slot < CAP) {
                                cj[row * CAP + slot] =
                                    j0 + wn * 32 + nf * 8 + t4 * 2 + cp;
                                cv[row * CAP + slot] = v;
                            }
                        }
                    }
            }

        CP_WAIT0();        // next B tile resident
        __syncthreads();   // candidate writes + buffer handoff
    }

    // ---- exact fp32 refinement (one thread per row)
    if (tid < TILE_M) {
        const int row = tid;
        const unsigned n = cnt[row];
        const float4* arow =
            (const float4*)(s1 + ((size_t)b * T1C + i0 + row) * DD);
        float best = __int_as_float(0xff800000);
        int bestj = 0;
        if (n <= CAP) {
            const float thr = dec(rmx[row]) - MARGIN;  // final max pruning
            for (unsigned k = 0; k < n; k++) {
                if (cv[row * CAP + k] < thr) continue;
                int j = cj[row * CAP + k];
                float d = dot256(arow,
                    (const float4*)(s2 + ((size_t)b * T2C + j) * DD));
                if (d > best || (d == best && j < bestj)) { best = d; bestj = j; }
            }
        } else {
            // overflow fallback: exact scan of the full row (ascending j,
            // strict '>' keeps the first max = numpy tie rule)
            for (int j = 0; j < T2C; j++) {
                float d = dot256(arow,
                    (const float4*)(s2 + ((size_t)b * T2C + j) * DD));
                if (d > best) { best = d; bestj = j; }
            }
        }
        g_argmax[b * T1C + i0 + row] = bestj;
    }
}

// ---------------------------------------------------------------------------
// gather + one-hot write (one warp per output row)
// ---------------------------------------------------------------------------
__global__ void __launch_bounds__(256)
gather_onehot_kernel(const float* __restrict__ s2, float* __restrict__ out)
{
    const int w    = threadIdx.x >> 5;
    const int lane = threadIdx.x & 31;
    const int r    = blockIdx.x * 8 + w;     // 0 .. BB*T1C-1
    const int b    = r >> 11;
    const int i    = r & (T1C - 1);
    const int j    = g_argmax[r];

    const float4* src = (const float4*)(s2 + ((size_t)b * T2C + (size_t)j) * DD);
    float4*       dst = (float4*)(out + (size_t)r * DD);
    dst[lane]      = src[lane];
    dst[lane + 32] = src[lane + 32];

    if (lane == 0)
        out[(size_t)BB * T1C * DD + (size_t)b * T1C * T2C +
            (size_t)i * T2C + j] = 1.0f;
}

// ---------------------------------------------------------------------------
// host
// ---------------------------------------------------------------------------
extern "C" void kernel_launch(void* const* d_in, const int* in_sizes, int n_in,
                              void* d_out, int out_size)
{
    (void)in_sizes; (void)n_in; (void)out_size;
    const float* s1 = (const float*)d_in[0];
    const float* s2 = (const float*)d_in[1];
    float* out = (float*)d_out;

    convert_kernel<<<2048, 256>>>((const float4*)s1, (const float4*)s2);

    cudaFuncSetAttribute(mma_argmax_kernel,
                         cudaFuncAttributeMaxDynamicSharedMemorySize,
                         SMEM_TOTAL);
    dim3 grid(T1C / TILE_M, BB);
    mma_argmax_kernel<<<grid, 256, SMEM_TOTAL>>>(s1, s2);

    // zero the one-hot region (u_tile region is fully overwritten by gather)
    cudaMemsetAsync(out + (size_t)BB * T1C * DD, 0,
                    (size_t)BB * T1C * T2C * sizeof(float));

    gather_onehot_kernel<<<(BB * T1C) / 8, 256>>>(s2, out);
}

// round 5
// speedup vs baseline: 8.4914x; 8.4914x over previous
#include <cuda_runtime.h>
#include <cstdint>
#include <cstddef>
#include <cfloat>

// Problem shape
#define BB   8
#define T1C  2048
#define T2C  2048
#define DD   256
#define NG   (DD / 4)          // 64 int32 k-groups per row

// GEMM tiling
#define TILE_M 128
#define TILE_N 128
#define N_JT   (T2C / TILE_N)  // 16
#define CAND_CAP 8192

// smem layout (bytes)
#define SM_AS   0                      // As[64][128] int32       (32768)
#define SM_BS   32768                  // Bs[2][64][128] int32    (65536)
#define SM_ALA  98304                  // alphaA[128] float
#define SM_L1A  98816                  // l1A[128] float
#define SM_RLB  99328                  // rowlb[128] uint (enc)
#define SM_BST  99840                  // best[128] u64 packed
#define SM_CND  100864                 // cand[8192] int
#define SM_MISC 133632                 // cnt, ovf
#define SMEM_TOTAL 133696

// int8 quantized inputs, k-major: q[b][g][idx]
__device__ int   g_q1[BB * NG * T1C];
__device__ int   g_q2[BB * NG * T2C];
__device__ float g_sc1[BB * T1C], g_l11[BB * T1C];
__device__ float g_sc2[BB * T2C], g_l12[BB * T2C];
__device__ int   g_argmax[BB * T1C];

// ---------------------------------------------------------------------------
// helpers
// ---------------------------------------------------------------------------
static __device__ __forceinline__ uint32_t smem_to_u32(const void* p) {
    uint32_t a;
    asm("{ .reg .u64 t; cvta.to.shared.u64 t, %1; cvt.u32.u64 %0, t; }"
        : "=r"(a) : "l"(p));
    return a;
}
static __device__ __forceinline__ void cp16(uint32_t dst, const void* src) {
    asm volatile("cp.async.cg.shared.global [%0], [%1], 16;"
                 :: "r"(dst), "l"(src));
}
#define CP_COMMIT() asm volatile("cp.async.commit_group;" ::: "memory")
#define CP_WAIT0()  asm volatile("cp.async.wait_group 0;" ::: "memory")

static __device__ __forceinline__ int dp4a_(int a, int b, int c) {
    int d;
    asm("dp4a.s32.s32 %0, %1, %2, %3;" : "=r"(d) : "r"(a), "r"(b), "r"(c));
    return d;
}
// order-preserving float<->uint encoding
static __device__ __forceinline__ unsigned enc(float x) {
    unsigned u = __float_as_uint(x);
    return (u & 0x80000000u) ? ~u : (u | 0x80000000u);
}
static __device__ __forceinline__ float dec(unsigned u) {
    return __uint_as_float((u & 0x80000000u) ? (u & 0x7FFFFFFFu) : ~u);
}

// exact fp32 dot of two 256-float rows
static __device__ float dot256(const float4* __restrict__ a,
                               const float4* __restrict__ b)
{
    float a0 = 0.f, a1 = 0.f, a2 = 0.f, a3 = 0.f;
    #pragma unroll 8
    for (int k = 0; k < DD / 4; k++) {
        float4 x = __ldg(a + k);
        float4 y = __ldg(b + k);
        a0 = fmaf(x.x, y.x, a0);
        a1 = fmaf(x.y, y.y, a1);
        a2 = fmaf(x.z, y.z, a2);
        a3 = fmaf(x.w, y.w, a3);
    }
    return (a0 + a1) + (a2 + a3);
}

// ---------------------------------------------------------------------------
// quantize: one warp per row; writes k-major packed int8 + per-row scale/L1
// ---------------------------------------------------------------------------
__global__ void __launch_bounds__(256)
quantize_kernel(const float4* __restrict__ s1, const float4* __restrict__ s2)
{
    const int w    = (blockIdx.x * 256 + threadIdx.x) >> 5;  // 0 .. 32767
    const int lane = threadIdx.x & 31;
    const bool is2 = w >= BB * T1C;
    const int r    = is2 ? w - BB * T1C : w;

    const float4* row = (is2 ? s2 : s1) + (size_t)r * (DD / 4);
    float4 v0 = __ldg(row + lane * 2);
    float4 v1 = __ldg(row + lane * 2 + 1);
    float vv[8] = {v0.x, v0.y, v0.z, v0.w, v1.x, v1.y, v1.z, v1.w};

    float am = 0.f, l1 = 0.f;
    #pragma unroll
    for (int k = 0; k < 8; k++) { float a = fabsf(vv[k]); am = fmaxf(am, a); l1 += a; }
    #pragma unroll
    for (int off = 16; off; off >>= 1) {
        am = fmaxf(am, __shfl_xor_sync(0xffffffffu, am, off));
        l1 += __shfl_xor_sync(0xffffffffu, l1, off);
    }
    const float inv   = am > 0.f ? 127.f / am : 0.f;
    const float alpha = am * (1.f / 127.f);

    int q[8];
    #pragma unroll
    for (int k = 0; k < 8; k++) {
        int qi = __float2int_rn(vv[k] * inv);
        q[k] = max(-127, min(127, qi));
    }
    const int p0 = (q[0] & 255) | ((q[1] & 255) << 8) |
                   ((q[2] & 255) << 16) | ((q[3] & 255) << 24);
    const int p1 = (q[4] & 255) | ((q[5] & 255) << 8) |
                   ((q[6] & 255) << 16) | ((q[7] & 255) << 24);

    const int b = r >> 11, i = r & 2047;
    int* dst = (is2 ? g_q2 : g_q1) + ((size_t)(b * NG + 2 * lane)) * 2048 + i;
    dst[0]    = p0;
    dst[2048] = p1;
    if (lane == 0) {
        (is2 ? g_sc2 : g_sc1)[r] = alpha;
        (is2 ? g_l12 : g_l11)[r] = l1;
    }
}

// ---------------------------------------------------------------------------
// int8 dp4a GEMM + certified argmax screen + exact fp32 refine.
// Grid (16, 8): bx = 128-row i-tile, by = batch. 256 threads.
// Thread microtile: 16 i x 4 j, int32 accumulators (exact).
// ---------------------------------------------------------------------------
__global__ void __launch_bounds__(256, 1)
gemm_argmax_kernel(const float* __restrict__ s1, const float* __restrict__ s2,
                   float* __restrict__ out)
{
    extern __shared__ __align__(16) char smem[];
    const uint32_t sb = smem_to_u32(smem);
    float*    alA   = (float*)(smem + SM_ALA);
    float*    l1A   = (float*)(smem + SM_L1A);
    unsigned* rowlb = (unsigned*)(smem + SM_RLB);
    unsigned long long* best = (unsigned long long*)(smem + SM_BST);
    int*      cand  = (int*)(smem + SM_CND);
    unsigned* cnt   = (unsigned*)(smem + SM_MISC);
    unsigned* ovf   = cnt + 1;

    const int tid = threadIdx.x;
    const int wid = tid >> 5, lane = tid & 31;
    const int ti  = wid;          // i-group of 16 rows (warp-uniform)
    const int tj  = lane;         // j-group of 4
    const int b   = blockIdx.y;
    const int i0  = blockIdx.x * TILE_M;

    // ---- stage A (all 64 k-groups of the i-tile) + B tile 0
    #pragma unroll
    for (int it = 0; it < 8; it++) {
        int f = tid + it * 256, g = f >> 5, c = f & 31;
        cp16(sb + SM_AS + g * 512 + c * 16,
             g_q1 + ((size_t)(b * NG + g)) * 2048 + i0 + c * 4);
    }
    #pragma unroll
    for (int it = 0; it < 8; it++) {
        int f = tid + it * 256, g = f >> 5, c = f & 31;
        cp16(sb + SM_BS + g * 512 + c * 16,
             g_q2 + ((size_t)(b * NG + g)) * 2048 + c * 4);
    }
    CP_COMMIT();

    // ---- zero this CTA's slice of the one-hot output region (replaces memset)
    {
        float4 z = make_float4(0.f, 0.f, 0.f, 0.f);
        float4* oz = (float4*)(out + (size_t)BB * T1C * DD) +
                     (size_t)(blockIdx.y * 16 + blockIdx.x) * 65536;
        #pragma unroll 8
        for (int it = 0; it < 256; it++) oz[tid + it * 256] = z;
    }

    // ---- smem init
    if (tid < TILE_M) {
        alA[tid]   = g_sc1[(b << 11) + i0 + tid];
        l1A[tid]   = g_l11[(b << 11) + i0 + tid];
        rowlb[tid] = 0x007FFFFFu;   // enc(-inf)
        best[tid]  = 0ull;
    }
    if (tid == 0) { *cnt = 0u; *ovf = 0u; }

    CP_WAIT0();
    __syncthreads();

    int acc[16][4];

    #pragma unroll 1
    for (int jc = 0; jc < N_JT; jc++) {
        const int buf = jc & 1;
        const int j0  = jc * TILE_N;

        if (jc + 1 < N_JT) {
            const int jn = j0 + TILE_N;
            #pragma unroll
            for (int it = 0; it < 8; it++) {
                int f = tid + it * 256, g = f >> 5, c = f & 31;
                cp16(sb + SM_BS + (buf ^ 1) * 32768 + g * 512 + c * 16,
                     g_q2 + ((size_t)(b * NG + g)) * 2048 + jn + c * 4);
            }
            CP_COMMIT();
        }

        #pragma unroll
        for (int ii = 0; ii < 16; ii++)
            #pragma unroll
            for (int q = 0; q < 4; q++) acc[ii][q] = 0;

        const char* Ab = smem + SM_AS + ti * 64;
        const char* Bb = smem + SM_BS + buf * 32768 + tj * 16;
        #pragma unroll 4
        for (int g = 0; g < NG; g++) {
            int4 a0 = *(const int4*)(Ab + g * 512);
            int4 a1 = *(const int4*)(Ab + g * 512 + 16);
            int4 a2 = *(const int4*)(Ab + g * 512 + 32);
            int4 a3 = *(const int4*)(Ab + g * 512 + 48);
            int4 bv = *(const int4*)(Bb + g * 512);
            int av[16] = {a0.x, a0.y, a0.z, a0.w, a1.x, a1.y, a1.z, a1.w,
                          a2.x, a2.y, a2.z, a2.w, a3.x, a3.y, a3.z, a3.w};
            int bw[4]  = {bv.x, bv.y, bv.z, bv.w};
            #pragma unroll
            for (int ii = 0; ii < 16; ii++)
                #pragma unroll
                for (int q = 0; q < 4; q++)
                    acc[ii][q] = dp4a_(av[ii], bw[q], acc[ii][q]);
        }

        // per-q scale data
        float bb4[4], lb4[4];
        #pragma unroll
        for (int q = 0; q < 4; q++) {
            int j = j0 + tj * 4 + q;
            bb4[q] = __ldg(g_sc2 + (b << 11) + j);
            lb4[q] = __ldg(g_l12 + (b << 11) + j);
        }

        // ---- phase A: per-row lower bound  lb = approx - M
        //   approx = aa*bb*S ;  M = 0.515*(bb*l1a + aa*l1b) + 68*aa*bb
        #pragma unroll
        for (int ii = 0; ii < 16; ii++) {
            const float aa = alA[ti * 16 + ii], la = l1A[ti * 16 + ii];
            const float k1 = 0.515f * la + 68.f * aa;
            const float c2 = 0.515f * aa;
            float m = -FLT_MAX;
            #pragma unroll
            for (int q = 0; q < 4; q++) {
                float t  = fmaf(aa, (float)acc[ii][q], -k1);
                float lb = fmaf(bb4[q], t, -c2 * lb4[q]);
                m = fmaxf(m, lb);
            }
            #pragma unroll
            for (int off = 16; off; off >>= 1)
                m = fmaxf(m, __shfl_xor_sync(0xffffffffu, m, off));
            if (lane == 0) atomicMax(&rowlb[ti * 16 + ii], enc(m));
        }
        __syncthreads();

        // ---- phase B: append every j whose upper bound reaches the row bound
        #pragma unroll
        for (int ii = 0; ii < 16; ii++) {
            const int row = ti * 16 + ii;
            const float aa = alA[row], la = l1A[row];
            const float k1 = 0.515f * la + 68.f * aa;
            const float c2 = 0.515f * aa;
            const float thr = dec(rowlb[row]);
            #pragma unroll
            for (int q = 0; q < 4; q++) {
                float t  = fmaf(aa, (float)acc[ii][q], k1);
                float ub = fmaf(bb4[q], t, c2 * lb4[q]);
                if (ub >= thr) {
                    unsigned pos = atomicAdd(cnt, 1u);
                    if (pos < CAND_CAP)
                        cand[pos] = (row << 11) | (j0 + tj * 4 + q);
                    else
                        *ovf = 1u;
                }
            }
        }

        CP_WAIT0();
        __syncthreads();
    }

    // ---- exact fp32 refinement
    const float* s1b = s1 + ((size_t)(b << 11) + i0) * DD;
    const float* s2b = s2 + ((size_t)(b << 11)) * DD;

    if (!*ovf) {
        const int n = (int)min(*cnt, (unsigned)CAND_CAP);
        for (int e = tid; e < n; e += 256) {
            int ent = cand[e];
            int row = ent >> 11, j = ent & 2047;
            float d = dot256((const float4*)(s1b + (size_t)row * DD),
                             (const float4*)(s2b + (size_t)j * DD));
            unsigned long long pk =
                ((unsigned long long)enc(d) << 32) | (unsigned)(2047 - j);
            atomicMax(&best[row], pk);
        }
    } else {
        // (near-impossible) fallback: exact warp-per-row scan
        for (int row = wid; row < TILE_M; row += 8) {
            float bv = -FLT_MAX; int bj = 0;
            for (int j = lane; j < T2C; j += 32) {
                float d = dot256((const float4*)(s1b + (size_t)row * DD),
                                 (const float4*)(s2b + (size_t)j * DD));
                if (d > bv || (d == bv && j < bj)) { bv = d; bj = j; }
            }
            unsigned long long pk =
                ((unsigned long long)enc(bv) << 32) | (unsigned)(2047 - bj);
            #pragma unroll
            for (int off = 16; off; off >>= 1) {
                unsigned long long o = __shfl_xor_sync(0xffffffffu, pk, off);
                if (o > pk) pk = o;
            }
            if (lane == 0) best[row] = pk;
        }
    }
    __syncthreads();

    if (tid < TILE_M) {
        int j = 2047 - (int)(best[tid] & 0xFFFFFFFFull);
        g_argmax[(b << 11) + i0 + tid] = j;
    }
}

// ---------------------------------------------------------------------------
// gather + one-hot write (one warp per output row)
// ---------------------------------------------------------------------------
__global__ void __launch_bounds__(256)
gather_onehot_kernel(const float* __restrict__ s2, float* __restrict__ out)
{
    const int w    = threadIdx.x >> 5;
    const int lane = threadIdx.x & 31;
    const int r    = blockIdx.x * 8 + w;     // 0 .. BB*T1C-1
    const int b    = r >> 11;
    const int i    = r & (T1C - 1);
    const int j    = g_argmax[r];

    const float4* src = (const float4*)(s2 + ((size_t)b * T2C + (size_t)j) * DD);
    float4*       dst = (float4*)(out + (size_t)r * DD);
    dst[lane]      = src[lane];
    dst[lane + 32] = src[lane + 32];

    if (lane == 0)
        out[(size_t)BB * T1C * DD + (size_t)b * T1C * T2C +
            (size_t)i * T2C + j] = 1.0f;
}

// ---------------------------------------------------------------------------
// host
// ---------------------------------------------------------------------------
extern "C" void kernel_launch(void* const* d_in, const int* in_sizes, int n_in,
                              void* d_out, int out_size)
{
    (void)in_sizes; (void)n_in; (void)out_size;
    const float* s1 = (const float*)d_in[0];
    const float* s2 = (const float*)d_in[1];
    float* out = (float*)d_out;

    quantize_kernel<<<4096, 256>>>((const float4*)s1, (const float4*)s2);

    cudaFuncSetAttribute(gemm_argmax_kernel,
                         cudaFuncAttributeMaxDynamicSharedMemorySize,
                         SMEM_TOTAL);
    dim3 grid(T1C / TILE_M, BB);
    gemm_argmax_kernel<<<grid, 256, SMEM_TOTAL>>>(s1, s2, out);

    gather_onehot_kernel<<<(BB * T1C) / 8, 256>>>(s2, out);
}